// round 3
// baseline (speedup 1.0000x reference)
#include <cuda_runtime.h>

#define NB 32
#define NL 100
#define NT (NB*NL)      // 3200 tokens
#define ND 200
#define INDIM 360
#define EMBD 300
#define POSD 30
#define NERD 30
#define NREL 40

#define BM 64           // tokens per block tile (GEMM)
#define BN 64           // outputs per block tile (GEMM)
#define KC 16           // k chunk
#define AGG_ROWS 10     // l rows per agg block (2 halves x 5)

typedef unsigned long long ull;

__device__ float g_xb[NT*ND];
__device__ float g_z[NT*ND];
__device__ float g_invden[NT];

// packed f32x2 helpers --------------------------------------------------------
__device__ __forceinline__ void fma2(ull& acc, ull a, ull b) {
    asm("fma.rn.f32x2 %0, %1, %2, %0;" : "+l"(acc) : "l"(a), "l"(b));
}
__device__ __forceinline__ ull splat2(float v) {
    ull r; unsigned u = __float_as_uint(v);
    asm("mov.b64 %0, {%1, %1};" : "=l"(r) : "r"(u));
    return r;
}
__device__ __forceinline__ void unpack2(ull a, float& lo, float& hi) {
    unsigned l, h;
    asm("mov.b64 {%0, %1}, %2;" : "=r"(l), "=r"(h) : "l"(a));
    lo = __uint_as_float(l); hi = __uint_as_float(h);
}

// ---------------------------------------------------------------------------
// denom + mask: adj[b] staged in smem, then row/col nonzero counts
// ---------------------------------------------------------------------------
__global__ void denom_mask_kernel(const int* __restrict__ adj,
                                  float* __restrict__ out_mask,
                                  int write_mask) {
    __shared__ int A[NL*NL];     // 40 KB
    int b = blockIdx.x;
    int tid = threadIdx.x;
    const int* src = adj + b*NL*NL;
    for (int i = tid; i < NL*NL; i += blockDim.x) A[i] = src[i];
    __syncthreads();
    if (tid < NL) {
        int rc = 0, cc = 0;
        #pragma unroll 4
        for (int m = 0; m < NL; m++) {
            rc += (A[tid*NL + m] != 0);
            cc += (A[m*NL + tid] != 0);
        }
        g_invden[b*NL + tid] = 1.0f / (float)(rc + 1);
        if (write_mask)
            out_mask[b*NL + tid] = (rc + cc == 0) ? 1.0f : 0.0f;
    }
}

// ---------------------------------------------------------------------------
// Preprocessor GEMM with fused embedding gather:
//   C[t,j] = concat_emb(t)[0:360] . Wp[j,:] + bp[j]
// 64x64 tile, 256 thr, 4x4 per thread (packed f32x2 accumulators).
// ---------------------------------------------------------------------------
__global__ void gemm_pre_kernel(const int* __restrict__ words,
                                const int* __restrict__ pos,
                                const int* __restrict__ ner,
                                const float* __restrict__ emb,
                                const float* __restrict__ pos_emb,
                                const float* __restrict__ ner_emb,
                                const float* __restrict__ B,
                                const float* __restrict__ bias,
                                float* __restrict__ C) {
    __shared__ __align__(16) float As[KC][BM+4];
    __shared__ __align__(16) float Bs[KC][BN+4];
    __shared__ int ws[BM], ps[BM], ns[BM];
    const int K = INDIM;
    int tid = threadIdx.x;
    int tx = tid & 15, ty = tid >> 4;
    int t0 = blockIdx.x * BM;
    int j0 = blockIdx.y * BN;

    if (tid < BM) {
        int tok = t0 + tid;
        ws[tid] = words[tok]*EMBD;
        ps[tid] = pos[tok]*POSD;
        ns[tid] = ner[tok]*NERD;
    }
    __syncthreads();

    ull acc[4][2];
    #pragma unroll
    for (int i = 0; i < 4; i++) { acc[i][0] = 0ull; acc[i][1] = 0ull; }

    for (int kc = 0; kc < K; kc += KC) {
        int kw = K - kc; if (kw > KC) kw = KC;
        #pragma unroll
        for (int it = 0; it < (BM*KC)/256; it++) {
            int idx = tid + it*256;
            int kk = idx & (KC-1);
            int t  = idx >> 4;
            int k  = kc + kk;
            float v = 0.f;
            if (kk < kw) {
                if (k < EMBD)           v = emb[ws[t] + k];
                else if (k < EMBD+POSD) v = pos_emb[ps[t] + (k - EMBD)];
                else                    v = ner_emb[ns[t] + (k - EMBD - POSD)];
            }
            As[kk][t] = v;
        }
        #pragma unroll
        for (int it = 0; it < (BN*KC)/256; it++) {
            int idx = tid + it*256;
            int kk = idx & (KC-1);
            int j  = idx >> 4;
            Bs[kk][j] = (kk < kw && (j0 + j) < ND) ? B[(j0 + j)*K + kc + kk] : 0.f;
        }
        __syncthreads();
        #pragma unroll
        for (int kk = 0; kk < KC; kk++) {
            float4 a = *(const float4*)&As[kk][4*tx];
            const ull* bp = (const ull*)&Bs[kk][4*ty];
            ull b01 = bp[0], b23 = bp[1];
            ull a0 = splat2(a.x), a1 = splat2(a.y), a2 = splat2(a.z), a3 = splat2(a.w);
            fma2(acc[0][0], a0, b01); fma2(acc[0][1], a0, b23);
            fma2(acc[1][0], a1, b01); fma2(acc[1][1], a1, b23);
            fma2(acc[2][0], a2, b01); fma2(acc[2][1], a2, b23);
            fma2(acc[3][0], a3, b01); fma2(acc[3][1], a3, b23);
        }
        __syncthreads();
    }

    int tbase = t0 + 4*tx;
    int jbase = j0 + 4*ty;
    #pragma unroll
    for (int i = 0; i < 4; i++) {
        int tok = tbase + i;
        #pragma unroll
        for (int jh = 0; jh < 2; jh++) {
            float f0, f1; unpack2(acc[i][jh], f0, f1);
            int j = jbase + 2*jh;
            if (j   < ND) C[tok*ND + j]   = f0 + bias[j];
            if (j+1 < ND) C[tok*ND + j+1] = f1 + bias[j+1];
        }
    }
}

// ---------------------------------------------------------------------------
// Layer GEMM: C[t,j] = relu((Z[t,:].W[j,:] + 2*b[j]) * invden[t])
// ---------------------------------------------------------------------------
__global__ void gemm_relu_kernel(const float* __restrict__ A,
                                 const float* __restrict__ B,
                                 const float* __restrict__ bias,
                                 float* __restrict__ C) {
    __shared__ __align__(16) float As[KC][BM+4];
    __shared__ __align__(16) float Bs[KC][BN+4];
    const int K = ND;
    int tid = threadIdx.x;
    int tx = tid & 15, ty = tid >> 4;
    int t0 = blockIdx.x * BM;
    int j0 = blockIdx.y * BN;

    ull acc[4][2];
    #pragma unroll
    for (int i = 0; i < 4; i++) { acc[i][0] = 0ull; acc[i][1] = 0ull; }

    for (int kc = 0; kc < K; kc += KC) {
        int kw = K - kc; if (kw > KC) kw = KC;
        #pragma unroll
        for (int it = 0; it < (BM*KC)/256; it++) {
            int idx = tid + it*256;
            int kk = idx & (KC-1);
            int t  = idx >> 4;
            As[kk][t] = (kk < kw) ? A[(t0 + t)*K + kc + kk] : 0.f;
        }
        #pragma unroll
        for (int it = 0; it < (BN*KC)/256; it++) {
            int idx = tid + it*256;
            int kk = idx & (KC-1);
            int j  = idx >> 4;
            Bs[kk][j] = (kk < kw && (j0 + j) < ND) ? B[(j0 + j)*K + kc + kk] : 0.f;
        }
        __syncthreads();
        #pragma unroll
        for (int kk = 0; kk < KC; kk++) {
            float4 a = *(const float4*)&As[kk][4*tx];
            const ull* bp = (const ull*)&Bs[kk][4*ty];
            ull b01 = bp[0], b23 = bp[1];
            ull a0 = splat2(a.x), a1 = splat2(a.y), a2 = splat2(a.z), a3 = splat2(a.w);
            fma2(acc[0][0], a0, b01); fma2(acc[0][1], a0, b23);
            fma2(acc[1][0], a1, b01); fma2(acc[1][1], a1, b23);
            fma2(acc[2][0], a2, b01); fma2(acc[2][1], a2, b23);
            fma2(acc[3][0], a3, b01); fma2(acc[3][1], a3, b23);
        }
        __syncthreads();
    }

    int tbase = t0 + 4*tx;
    int jbase = j0 + 4*ty;
    #pragma unroll
    for (int i = 0; i < 4; i++) {
        int tok = tbase + i;
        float inv = g_invden[tok];
        #pragma unroll
        for (int jh = 0; jh < 2; jh++) {
            float f0, f1; unpack2(acc[i][jh], f0, f1);
            int j = jbase + 2*jh;
            if (j   < ND) C[tok*ND + j]   = fmaxf((f0 + 2.f*bias[j])   * inv, 0.f);
            if (j+1 < ND) C[tok*ND + j+1] = fmaxf((f1 + 2.f*bias[j+1]) * inv, 0.f);
        }
    }
}

// ---------------------------------------------------------------------------
// Aggregation: Z[b,l,d] = x[b,l,d] + sum_m E[adj[b,l,m], d] * x[b,m,d]
// f32x2-packed: thread owns d-pair; 10 rows/block (2 halves x 5 rows).
// adjsT holds byte offsets into Es (r * ND * 4), broadcast-read as int4+int.
// ---------------------------------------------------------------------------
__global__ void agg_kernel(const int* __restrict__ adj,
                           const float* __restrict__ dep,
                           const float* __restrict__ x,
                           float* __restrict__ z) {
    __shared__ __align__(16) float Es[NREL*ND];   // 32 KB
    __shared__ __align__(16) int adjsT[NL*16];    // 6.4 KB
    int tid = threadIdx.x;
    int b = blockIdx.y;
    int l0 = blockIdx.x * AGG_ROWS;

    for (int i = tid; i < NREL*ND; i += 256) Es[i] = dep[i];
    for (int i = tid; i < AGG_ROWS*NL; i += 256) {
        int j = i / NL, m = i - j*NL;
        int slot = (j < 5) ? j : j + 3;       // halves at cols [0..4] and [8..12]
        adjsT[m*16 + slot] = adj[(b*NL + l0 + j)*NL + m] * (ND*4);
    }
    __syncthreads();

    int half = tid >> 7;
    int dp = tid & 127;
    if (dp < ND/2) {
        int r0 = l0 + half*5;
        const char* ep = (const char*)Es + 8*dp;
        const float* xb = x + b*NL*ND + 2*dp;

        ull acc[5];
        #pragma unroll
        for (int i = 0; i < 5; i++)
            acc[i] = *(const ull*)&x[(b*NL + r0 + i)*ND + 2*dp];

        #pragma unroll 2
        for (int m = 0; m < NL; m++) {
            ull xv = *(const ull*)(xb + m*ND);
            const int4 r03 = *(const int4*)&adjsT[m*16 + half*8];
            const int  r4  = adjsT[m*16 + half*8 + 4];
            fma2(acc[0], *(const ull*)(ep + r03.x), xv);
            fma2(acc[1], *(const ull*)(ep + r03.y), xv);
            fma2(acc[2], *(const ull*)(ep + r03.z), xv);
            fma2(acc[3], *(const ull*)(ep + r03.w), xv);
            fma2(acc[4], *(const ull*)(ep + r4),    xv);
        }
        #pragma unroll
        for (int i = 0; i < 5; i++)
            *(ull*)&z[(b*NL + r0 + i)*ND + 2*dp] = acc[i];
    }
}

// ---------------------------------------------------------------------------
extern "C" void kernel_launch(void* const* d_in, const int* in_sizes, int n_in,
                              void* d_out, int out_size) {
    const int*   adj     = (const int*)  d_in[0];
    const int*   words   = (const int*)  d_in[1];
    const int*   pos     = (const int*)  d_in[2];
    const int*   ner     = (const int*)  d_in[3];
    const float* emb     = (const float*)d_in[4];
    const float* pos_emb = (const float*)d_in[5];
    const float* ner_emb = (const float*)d_in[6];
    const float* dep     = (const float*)d_in[7];
    const float* Wp      = (const float*)d_in[8];
    const float* bp      = (const float*)d_in[9];
    const float* W0      = (const float*)d_in[10];
    const float* b0      = (const float*)d_in[11];
    const float* W1      = (const float*)d_in[12];
    const float* b1      = (const float*)d_in[13];
    float* out = (float*)d_out;

    float *xb, *z;
    cudaGetSymbolAddress((void**)&xb, g_xb);
    cudaGetSymbolAddress((void**)&z,  g_z);

    int write_mask = (out_size >= NT*ND + NT) ? 1 : 0;

    dim3 ggrid(NT/BM, (ND + BN - 1)/BN);        // (50, 4)
    dim3 agrid(NL/AGG_ROWS, NB);                // (10, 32)

    denom_mask_kernel<<<NB, 256>>>(adj, out + NT*ND, write_mask);
    gemm_pre_kernel<<<ggrid, 256>>>(words, pos, ner, emb, pos_emb, ner_emb,
                                    Wp, bp, xb);
    agg_kernel<<<agrid, 256>>>(adj, dep, xb, z);
    gemm_relu_kernel<<<ggrid, 256>>>(z, W0, b0, xb);
    agg_kernel<<<agrid, 256>>>(adj, dep, xb, z);
    gemm_relu_kernel<<<ggrid, 256>>>(z, W1, b1, out);
}

// round 4
// speedup vs baseline: 1.2742x; 1.2742x over previous
#include <cuda_runtime.h>

#define NB 32
#define NL 100
#define NT (NB*NL)      // 3200 tokens
#define ND 200
#define INDIM 360
#define EMBD 300
#define POSD 30
#define NERD 30
#define NREL 40

#define BM 32           // tokens per block tile (GEMM)
#define BN 64           // outputs per block tile (GEMM)
#define KC 16           // k chunk
#define AGG_ROWS 5      // l rows per agg block

typedef unsigned long long ull;

__device__ float g_xa[NT*INDIM];
__device__ float g_xb[NT*ND];
__device__ float g_z[NT*ND];
__device__ float g_invden[NT];

__device__ __forceinline__ void fma2(ull& acc, ull a, ull b) {
    asm("fma.rn.f32x2 %0, %1, %2, %0;" : "+l"(acc) : "l"(a), "l"(b));
}

// ---------------------------------------------------------------------------
// denom + mask
// ---------------------------------------------------------------------------
__global__ void denom_mask_kernel(const int* __restrict__ adj,
                                  float* __restrict__ out_mask,
                                  int write_mask) {
    __shared__ int A[NL*NL];     // 40 KB
    int b = blockIdx.x;
    int tid = threadIdx.x;
    const int* src = adj + b*NL*NL;
    for (int i = tid; i < NL*NL; i += blockDim.x) A[i] = src[i];
    __syncthreads();
    if (tid < NL) {
        int rc = 0, cc = 0;
        #pragma unroll 4
        for (int m = 0; m < NL; m++) {
            rc += (A[tid*NL + m] != 0);
            cc += (A[m*NL + tid] != 0);
        }
        g_invden[b*NL + tid] = 1.0f / (float)(rc + 1);
        if (write_mask)
            out_mask[b*NL + tid] = (rc + cc == 0) ? 1.0f : 0.0f;
    }
}

// ---------------------------------------------------------------------------
// Embedding gather: one block per token
// ---------------------------------------------------------------------------
__global__ void gather_kernel(const int* __restrict__ words,
                              const int* __restrict__ pos,
                              const int* __restrict__ ner,
                              const float* __restrict__ emb,
                              const float* __restrict__ pos_emb,
                              const float* __restrict__ ner_emb,
                              float* __restrict__ xout) {
    int tok = blockIdx.x;
    int k = threadIdx.x;
    if (k >= INDIM) return;
    float v;
    if (k < EMBD)            v = emb[words[tok]*EMBD + k];
    else if (k < EMBD+POSD)  v = pos_emb[pos[tok]*POSD + (k - EMBD)];
    else                     v = ner_emb[ner[tok]*NERD + (k - EMBD - POSD)];
    xout[tok*INDIM + k] = v;
}

// ---------------------------------------------------------------------------
// Double-buffered register-tiled SGEMM: C[M x 200] = A[M x K] . B[200 x K]^T
// Block 32x64, 256 thr, 2x4 per thread. One __syncthreads per k-chunk;
// global loads of chunk c+1 overlap compute of chunk c.
// MODE 0: C = acc + bias[j]
// MODE 1: C = relu((acc + 2*bias[j]) * invden[t])
// ---------------------------------------------------------------------------
template<int K, int MODE>
__global__ __launch_bounds__(256) void gemm_kernel(const float* __restrict__ A,
                                                   const float* __restrict__ B,
                                                   const float* __restrict__ bias,
                                                   float* __restrict__ C) {
    const int NC = (K + KC - 1) / KC;
    __shared__ __align__(16) float As[2][KC][BM+4];
    __shared__ __align__(16) float Bs[2][KC][BN+4];
    int tid = threadIdx.x;
    int tx = tid & 15, ty = tid >> 4;
    int t0 = blockIdx.x * BM;
    int j0 = blockIdx.y * BN;

    // loader mapping: idx = tid + it*256; kk = idx&15; row = idx>>4
    int lkk = tid & 15;
    int lrow = tid >> 4;         // 0..15

    float rA[2], rB[4];

    // --- preload chunk 0 ---
    {
        #pragma unroll
        for (int it = 0; it < 2; it++) {
            int t = lrow + it*16;
            rA[it] = (lkk < K) ? A[(t0 + t)*K + lkk] : 0.f;
        }
        #pragma unroll
        for (int it = 0; it < 4; it++) {
            int j = lrow + it*16;
            rB[it] = (lkk < K && (j0 + j) < ND) ? B[(j0 + j)*K + lkk] : 0.f;
        }
        #pragma unroll
        for (int it = 0; it < 2; it++) As[0][lkk][lrow + it*16] = rA[it];
        #pragma unroll
        for (int it = 0; it < 4; it++) Bs[0][lkk][lrow + it*16] = rB[it];
    }
    __syncthreads();

    float acc[2][4];
    #pragma unroll
    for (int i = 0; i < 2; i++)
        #pragma unroll
        for (int j = 0; j < 4; j++) acc[i][j] = 0.f;

    for (int c = 0; c < NC; c++) {
        int cur = c & 1;
        // issue loads for chunk c+1
        if (c + 1 < NC) {
            int kc = (c + 1) * KC;
            int k = kc + lkk;
            #pragma unroll
            for (int it = 0; it < 2; it++) {
                int t = lrow + it*16;
                rA[it] = (k < K) ? A[(t0 + t)*K + k] : 0.f;
            }
            #pragma unroll
            for (int it = 0; it < 4; it++) {
                int j = lrow + it*16;
                rB[it] = (k < K && (j0 + j) < ND) ? B[(j0 + j)*K + k] : 0.f;
            }
        }
        // compute chunk c
        #pragma unroll
        for (int kk = 0; kk < KC; kk++) {
            float2 a = *(const float2*)&As[cur][kk][2*tx];
            float4 b = *(const float4*)&Bs[cur][kk][4*ty];
            acc[0][0] += a.x*b.x; acc[0][1] += a.x*b.y; acc[0][2] += a.x*b.z; acc[0][3] += a.x*b.w;
            acc[1][0] += a.y*b.x; acc[1][1] += a.y*b.y; acc[1][2] += a.y*b.z; acc[1][3] += a.y*b.w;
        }
        // store chunk c+1
        if (c + 1 < NC) {
            int nxt = cur ^ 1;
            #pragma unroll
            for (int it = 0; it < 2; it++) As[nxt][lkk][lrow + it*16] = rA[it];
            #pragma unroll
            for (int it = 0; it < 4; it++) Bs[nxt][lkk][lrow + it*16] = rB[it];
        }
        __syncthreads();
    }

    int tbase = t0 + 2*tx;
    int jbase = j0 + 4*ty;
    #pragma unroll
    for (int i = 0; i < 2; i++) {
        int tok = tbase + i;
        float inv = (MODE == 1) ? g_invden[tok] : 0.f;
        float4 v;
        if (MODE == 0) {
            v.x = acc[i][0] + bias[jbase];
            v.y = acc[i][1] + bias[jbase+1];
            v.z = acc[i][2] + bias[jbase+2];
            v.w = acc[i][3] + bias[jbase+3];
        } else {
            v.x = fmaxf((acc[i][0] + 2.f*bias[jbase])   * inv, 0.f);
            v.y = fmaxf((acc[i][1] + 2.f*bias[jbase+1]) * inv, 0.f);
            v.z = fmaxf((acc[i][2] + 2.f*bias[jbase+2]) * inv, 0.f);
            v.w = fmaxf((acc[i][3] + 2.f*bias[jbase+3]) * inv, 0.f);
        }
        if (jbase + 3 < ND)
            *(float4*)&C[tok*ND + jbase] = v;
        else {
            if (jbase   < ND) C[tok*ND + jbase]   = v.x;
            if (jbase+1 < ND) C[tok*ND + jbase+1] = v.y;
            if (jbase+2 < ND) C[tok*ND + jbase+2] = v.z;
            if (jbase+3 < ND) C[tok*ND + jbase+3] = v.w;
        }
    }
}

// ---------------------------------------------------------------------------
// Aggregation: Z[b,l,d] = x[b,l,d] + sum_m E[adj[b,l,m], d] * x[b,m,d]
// 5 rows per 128-thread block (grid 640). Thread owns a d-pair (f32x2).
// adjs holds byte offsets (r*ND*4), stride-8 so rows read as int4+int broadcast.
// ---------------------------------------------------------------------------
__global__ __launch_bounds__(128) void agg_kernel(const int* __restrict__ adj,
                                                  const float* __restrict__ dep,
                                                  const float* __restrict__ x,
                                                  float* __restrict__ z) {
    __shared__ __align__(16) float Es[NREL*ND];   // 32 KB
    __shared__ __align__(16) int adjs[NL*8];      // 3.2 KB
    int tid = threadIdx.x;
    int b = blockIdx.y;
    int l0 = blockIdx.x * AGG_ROWS;

    for (int i = tid; i < NREL*ND; i += 128) Es[i] = dep[i];
    for (int i = tid; i < AGG_ROWS*NL; i += 128) {
        int j = i / NL, m = i - j*NL;
        adjs[m*8 + j] = adj[(b*NL + l0 + j)*NL + m] * (ND*4);
    }
    __syncthreads();

    int dp = tid;
    if (dp < ND/2) {
        const char* ep = (const char*)Es + 8*dp;
        const float* xb = x + b*NL*ND + 2*dp;

        ull acc[AGG_ROWS];
        #pragma unroll
        for (int i = 0; i < AGG_ROWS; i++)
            acc[i] = *(const ull*)&x[(b*NL + l0 + i)*ND + 2*dp];

        #pragma unroll 2
        for (int m = 0; m < NL; m++) {
            ull xv = *(const ull*)(xb + m*ND);
            const int4 r03 = *(const int4*)&adjs[m*8];
            const int  r4  = adjs[m*8 + 4];
            fma2(acc[0], *(const ull*)(ep + r03.x), xv);
            fma2(acc[1], *(const ull*)(ep + r03.y), xv);
            fma2(acc[2], *(const ull*)(ep + r03.z), xv);
            fma2(acc[3], *(const ull*)(ep + r03.w), xv);
            fma2(acc[4], *(const ull*)(ep + r4),    xv);
        }
        #pragma unroll
        for (int i = 0; i < AGG_ROWS; i++)
            *(ull*)&z[(b*NL + l0 + i)*ND + 2*dp] = acc[i];
    }
}

// ---------------------------------------------------------------------------
extern "C" void kernel_launch(void* const* d_in, const int* in_sizes, int n_in,
                              void* d_out, int out_size) {
    const int*   adj     = (const int*)  d_in[0];
    const int*   words   = (const int*)  d_in[1];
    const int*   pos     = (const int*)  d_in[2];
    const int*   ner     = (const int*)  d_in[3];
    const float* emb     = (const float*)d_in[4];
    const float* pos_emb = (const float*)d_in[5];
    const float* ner_emb = (const float*)d_in[6];
    const float* dep     = (const float*)d_in[7];
    const float* Wp      = (const float*)d_in[8];
    const float* bp      = (const float*)d_in[9];
    const float* W0      = (const float*)d_in[10];
    const float* b0      = (const float*)d_in[11];
    const float* W1      = (const float*)d_in[12];
    const float* b1      = (const float*)d_in[13];
    float* out = (float*)d_out;

    float *xa, *xb, *z;
    cudaGetSymbolAddress((void**)&xa, g_xa);
    cudaGetSymbolAddress((void**)&xb, g_xb);
    cudaGetSymbolAddress((void**)&z,  g_z);

    int write_mask = (out_size >= NT*ND + NT) ? 1 : 0;

    dim3 ggrid(NT/BM, (ND + BN - 1)/BN);        // (100, 4) = 400 blocks
    dim3 agrid(NL/AGG_ROWS, NB);                // (20, 32) = 640 blocks

    denom_mask_kernel<<<NB, 256>>>(adj, out + NT*ND, write_mask);
    gather_kernel<<<NT, 384>>>(words, pos, ner, emb, pos_emb, ner_emb, xa);
    gemm_kernel<INDIM, 0><<<ggrid, 256>>>(xa, Wp, bp, xb);
    agg_kernel<<<agrid, 128>>>(adj, dep, xb, z);
    gemm_kernel<ND, 1><<<ggrid, 256>>>(z, W0, b0, xb);
    agg_kernel<<<agrid, 128>>>(adj, dep, xb, z);
    gemm_kernel<ND, 1><<<ggrid, 256>>>(z, W1, b1, out);
}

// round 6
// speedup vs baseline: 1.3591x; 1.0667x over previous
#include <cuda_runtime.h>

#define NB 32
#define NL 100
#define NT (NB*NL)      // 3200 tokens
#define ND 200
#define INDIM 360
#define EMBD 300
#define POSD 30
#define NERD 30
#define NREL 40

#define BM 32           // tokens per block tile (GEMM)
#define BN 64           // outputs per block tile (GEMM)
#define KC 16           // k chunk
#define AGG_ROWS 5      // l rows per agg block
#define MH 50           // m per half (two warp-groups split the m range)

typedef unsigned long long ull;

__device__ float g_xa[NT*INDIM];
__device__ float g_xb[NT*ND];
__device__ float g_z[NT*ND];
__device__ float g_invden[NT];

__device__ __forceinline__ void fma2(ull& acc, ull a, ull b) {
    asm("fma.rn.f32x2 %0, %1, %2, %0;" : "+l"(acc) : "l"(a), "l"(b));
}
__device__ __forceinline__ ull add2(ull a, ull b) {
    ull r;
    asm("add.rn.f32x2 %0, %1, %2;" : "=l"(r) : "l"(a), "l"(b));
    return r;
}

// ---------------------------------------------------------------------------
// denom + mask
// ---------------------------------------------------------------------------
__global__ void denom_mask_kernel(const int* __restrict__ adj,
                                  float* __restrict__ out_mask,
                                  int write_mask) {
    __shared__ int A[NL*NL];     // 40 KB
    int b = blockIdx.x;
    int tid = threadIdx.x;
    const int* src = adj + b*NL*NL;
    for (int i = tid; i < NL*NL; i += blockDim.x) A[i] = src[i];
    __syncthreads();
    if (tid < NL) {
        int rc = 0, cc = 0;
        #pragma unroll 4
        for (int m = 0; m < NL; m++) {
            rc += (A[tid*NL + m] != 0);
            cc += (A[m*NL + tid] != 0);
        }
        g_invden[b*NL + tid] = 1.0f / (float)(rc + 1);
        if (write_mask)
            out_mask[b*NL + tid] = (rc + cc == 0) ? 1.0f : 0.0f;
    }
}

// ---------------------------------------------------------------------------
// Embedding gather: one block per token
// ---------------------------------------------------------------------------
__global__ void gather_kernel(const int* __restrict__ words,
                              const int* __restrict__ pos,
                              const int* __restrict__ ner,
                              const float* __restrict__ emb,
                              const float* __restrict__ pos_emb,
                              const float* __restrict__ ner_emb,
                              float* __restrict__ xout) {
    int tok = blockIdx.x;
    int k = threadIdx.x;
    if (k >= INDIM) return;
    float v;
    if (k < EMBD)            v = emb[words[tok]*EMBD + k];
    else if (k < EMBD+POSD)  v = pos_emb[pos[tok]*POSD + (k - EMBD)];
    else                     v = ner_emb[ner[tok]*NERD + (k - EMBD - POSD)];
    xout[tok*INDIM + k] = v;
}

// ---------------------------------------------------------------------------
// Double-buffered register-tiled SGEMM: C[M x 200] = A[M x K] . B[200 x K]^T
// Block 32x64, 256 thr, 2x4 per thread. One __syncthreads per k-chunk.
// MODE 0: C = acc + bias[j]
// MODE 1: C = relu((acc + 2*bias[j]) * invden[t])
// ---------------------------------------------------------------------------
template<int K, int MODE>
__global__ __launch_bounds__(256) void gemm_kernel(const float* __restrict__ A,
                                                   const float* __restrict__ B,
                                                   const float* __restrict__ bias,
                                                   float* __restrict__ C) {
    const int NC = (K + KC - 1) / KC;
    __shared__ __align__(16) float As[2][KC][BM+4];
    __shared__ __align__(16) float Bs[2][KC][BN+4];
    int tid = threadIdx.x;
    int tx = tid & 15, ty = tid >> 4;
    int t0 = blockIdx.x * BM;
    int j0 = blockIdx.y * BN;

    int lkk = tid & 15;
    int lrow = tid >> 4;         // 0..15

    float rA[2], rB[4];

    // --- preload chunk 0 ---
    {
        #pragma unroll
        for (int it = 0; it < 2; it++) {
            int t = lrow + it*16;
            rA[it] = (lkk < K) ? A[(t0 + t)*K + lkk] : 0.f;
        }
        #pragma unroll
        for (int it = 0; it < 4; it++) {
            int j = lrow + it*16;
            rB[it] = (lkk < K && (j0 + j) < ND) ? B[(j0 + j)*K + lkk] : 0.f;
        }
        #pragma unroll
        for (int it = 0; it < 2; it++) As[0][lkk][lrow + it*16] = rA[it];
        #pragma unroll
        for (int it = 0; it < 4; it++) Bs[0][lkk][lrow + it*16] = rB[it];
    }
    __syncthreads();

    float acc[2][4];
    #pragma unroll
    for (int i = 0; i < 2; i++)
        #pragma unroll
        for (int j = 0; j < 4; j++) acc[i][j] = 0.f;

    for (int c = 0; c < NC; c++) {
        int cur = c & 1;
        if (c + 1 < NC) {
            int k = (c + 1) * KC + lkk;
            #pragma unroll
            for (int it = 0; it < 2; it++) {
                int t = lrow + it*16;
                rA[it] = (k < K) ? A[(t0 + t)*K + k] : 0.f;
            }
            #pragma unroll
            for (int it = 0; it < 4; it++) {
                int j = lrow + it*16;
                rB[it] = (k < K && (j0 + j) < ND) ? B[(j0 + j)*K + k] : 0.f;
            }
        }
        #pragma unroll
        for (int kk = 0; kk < KC; kk++) {
            float2 a = *(const float2*)&As[cur][kk][2*tx];
            float4 b = *(const float4*)&Bs[cur][kk][4*ty];
            acc[0][0] += a.x*b.x; acc[0][1] += a.x*b.y; acc[0][2] += a.x*b.z; acc[0][3] += a.x*b.w;
            acc[1][0] += a.y*b.x; acc[1][1] += a.y*b.y; acc[1][2] += a.y*b.z; acc[1][3] += a.y*b.w;
        }
        if (c + 1 < NC) {
            int nxt = cur ^ 1;
            #pragma unroll
            for (int it = 0; it < 2; it++) As[nxt][lkk][lrow + it*16] = rA[it];
            #pragma unroll
            for (int it = 0; it < 4; it++) Bs[nxt][lkk][lrow + it*16] = rB[it];
        }
        __syncthreads();
    }

    int tbase = t0 + 2*tx;
    int jbase = j0 + 4*ty;
    #pragma unroll
    for (int i = 0; i < 2; i++) {
        int tok = tbase + i;
        float inv = (MODE == 1) ? g_invden[tok] : 0.f;
        float4 v;
        if (MODE == 0) {
            v.x = acc[i][0] + bias[jbase];
            v.y = acc[i][1] + bias[jbase+1];
            v.z = acc[i][2] + bias[jbase+2];
            v.w = acc[i][3] + bias[jbase+3];
        } else {
            v.x = fmaxf((acc[i][0] + 2.f*bias[jbase])   * inv, 0.f);
            v.y = fmaxf((acc[i][1] + 2.f*bias[jbase+1]) * inv, 0.f);
            v.z = fmaxf((acc[i][2] + 2.f*bias[jbase+2]) * inv, 0.f);
            v.w = fmaxf((acc[i][3] + 2.f*bias[jbase+3]) * inv, 0.f);
        }
        if (jbase + 3 < ND)
            *(float4*)&C[tok*ND + jbase] = v;
        else {
            if (jbase   < ND) C[tok*ND + jbase]   = v.x;
            if (jbase+1 < ND) C[tok*ND + jbase+1] = v.y;
            if (jbase+2 < ND) C[tok*ND + jbase+2] = v.z;
            if (jbase+3 < ND) C[tok*ND + jbase+3] = v.w;
        }
    }
}

// ---------------------------------------------------------------------------
// Aggregation: Z[b,l,d] = x[b,l,d] + sum_m E[adj[b,l,m], d] * x[b,m,d]
// 256 threads: two warp-groups split the m range (0..49 / 50..99); each thread
// owns a d-pair (f32x2). x loads software-pipelined in exact chunks of 5
// (MH=50 -> 10 iterations, no tail). Halves combined via smem partial buffer.
// ---------------------------------------------------------------------------
__global__ __launch_bounds__(256) void agg_kernel(const int* __restrict__ adj,
                                                  const float* __restrict__ dep,
                                                  const float* __restrict__ x,
                                                  float* __restrict__ z) {
    __shared__ __align__(16) float Es[NREL*ND];        // 32 KB
    __shared__ __align__(16) int adjs[NL*8];           // 3.2 KB
    __shared__ __align__(16) float part[AGG_ROWS][ND]; // 4 KB
    int tid = threadIdx.x;
    int b = blockIdx.y;
    int l0 = blockIdx.x * AGG_ROWS;

    for (int i = tid; i < NREL*ND; i += 256) Es[i] = dep[i];
    for (int i = tid; i < AGG_ROWS*NL; i += 256) {
        int j = i / NL, m = i - j*NL;
        adjs[m*8 + j] = adj[(b*NL + l0 + j)*NL + m] * (ND*4);
    }
    __syncthreads();

    int dp = tid & 127;
    int mh = tid >> 7;           // which m-half
    bool active = dp < ND/2;

    ull acc[AGG_ROWS];
    if (active) {
        const char* ep = (const char*)Es + 8*dp;
        const float* xb = x + b*NL*ND + 2*dp + mh*MH*ND;
        const int*  ap = adjs + mh*MH*8;

        if (mh == 0) {
            #pragma unroll
            for (int i = 0; i < AGG_ROWS; i++)
                acc[i] = *(const ull*)&x[(b*NL + l0 + i)*ND + 2*dp];
        } else {
            #pragma unroll
            for (int i = 0; i < AGG_ROWS; i++) acc[i] = 0ull;
        }

        // prefetch pipeline: exact chunks of 5 (50 = 10 x 5)
        ull xv[5];
        #pragma unroll
        for (int s = 0; s < 5; s++) xv[s] = *(const ull*)(xb + s*ND);

        #pragma unroll 1
        for (int m = 0; m < MH; m += 5) {
            ull cv[5];
            #pragma unroll
            for (int s = 0; s < 5; s++) cv[s] = xv[s];
            if (m + 5 < MH) {
                #pragma unroll
                for (int s = 0; s < 5; s++)
                    xv[s] = *(const ull*)(xb + (m + 5 + s)*ND);
            }
            #pragma unroll
            for (int s = 0; s < 5; s++) {
                const int4 r03 = *(const int4*)&ap[(m+s)*8];
                const int  r4  = ap[(m+s)*8 + 4];
                fma2(acc[0], *(const ull*)(ep + r03.x), cv[s]);
                fma2(acc[1], *(const ull*)(ep + r03.y), cv[s]);
                fma2(acc[2], *(const ull*)(ep + r03.z), cv[s]);
                fma2(acc[3], *(const ull*)(ep + r03.w), cv[s]);
                fma2(acc[4], *(const ull*)(ep + r4),    cv[s]);
            }
        }

        if (mh == 1) {
            #pragma unroll
            for (int i = 0; i < AGG_ROWS; i++)
                *(ull*)&part[i][2*dp] = acc[i];
        }
    }
    __syncthreads();
    if (active && mh == 0) {
        #pragma unroll
        for (int i = 0; i < AGG_ROWS; i++) {
            ull p = *(const ull*)&part[i][2*dp];
            *(ull*)&z[(b*NL + l0 + i)*ND + 2*dp] = add2(acc[i], p);
        }
    }
}

// ---------------------------------------------------------------------------
extern "C" void kernel_launch(void* const* d_in, const int* in_sizes, int n_in,
                              void* d_out, int out_size) {
    const int*   adj     = (const int*)  d_in[0];
    const int*   words   = (const int*)  d_in[1];
    const int*   pos     = (const int*)  d_in[2];
    const int*   ner     = (const int*)  d_in[3];
    const float* emb     = (const float*)d_in[4];
    const float* pos_emb = (const float*)d_in[5];
    const float* ner_emb = (const float*)d_in[6];
    const float* dep     = (const float*)d_in[7];
    const float* Wp      = (const float*)d_in[8];
    const float* bp      = (const float*)d_in[9];
    const float* W0      = (const float*)d_in[10];
    const float* b0      = (const float*)d_in[11];
    const float* W1      = (const float*)d_in[12];
    const float* b1      = (const float*)d_in[13];
    float* out = (float*)d_out;

    float *xa, *xb, *z;
    cudaGetSymbolAddress((void**)&xa, g_xa);
    cudaGetSymbolAddress((void**)&xb, g_xb);
    cudaGetSymbolAddress((void**)&z,  g_z);

    int write_mask = (out_size >= NT*ND + NT) ? 1 : 0;

    dim3 ggrid(NT/BM, (ND + BN - 1)/BN);        // (100, 4) = 400 blocks
    dim3 agrid(NL/AGG_ROWS, NB);                // (20, 32) = 640 blocks

    denom_mask_kernel<<<NB, 256>>>(adj, out + NT*ND, write_mask);
    gather_kernel<<<NT, 384>>>(words, pos, ner, emb, pos_emb, ner_emb, xa);
    gemm_kernel<INDIM, 0><<<ggrid, 256>>>(xa, Wp, bp, xb);
    agg_kernel<<<agrid, 256>>>(adj, dep, xb, z);
    gemm_kernel<ND, 1><<<ggrid, 256>>>(z, W0, b0, xb);
    agg_kernel<<<agrid, 256>>>(adj, dep, xb, z);
    gemm_kernel<ND, 1><<<ggrid, 256>>>(z, W1, b1, out);
}